// round 1
// baseline (speedup 1.0000x reference)
#include <cuda_runtime.h>

// Problem dimensions (fixed by the dataset)
#define U_DIM 16384
#define I_DIM 16384
#define G_DIM 4096
#define N_DIM 36864
#define D_DIM 128
#define BIAS_C (-0.73f)

#define SPLITS 16   // split-K factor for the two G-output GEMMs

// Scratch (device globals: allocation-free per harness rules)
__device__ float g_partial[2 * SPLITS * G_DIM * D_DIM];  // 64 MB split-K partials
__device__ float g_umsg[G_DIM * D_DIM];
__device__ float g_imsg[G_DIM * D_DIM];
__device__ float g_msg[G_DIM * D_DIM];                   // fallback msg buffer

// ---------------------------------------------------------------------------
// Generic C[M,128] = A[M,K] @ B[K,128], BM=BN=128, BK=16, 256 threads,
// 8x8 microtile per thread. blockIdx.y = split-K chunk, blockIdx.z selects
// (A0,B0) vs (A1,B1) so independent GEMMs pack into one launch.
// ---------------------------------------------------------------------------
__global__ __launch_bounds__(256, 2)
void sgemm128(const float* __restrict__ A0, const float* __restrict__ B0,
              const float* __restrict__ A1, const float* __restrict__ B1,
              float* __restrict__ C, int K, int kLen,
              long cSplitStride, long cZStride)
{
    __shared__ float As[16][132];   // transposed A tile, padded vs bank conflicts
    __shared__ float Bs[16][128];

    const int tid = threadIdx.x;
    const int z = blockIdx.z;
    const float* __restrict__ A = z ? A1 : A0;
    const float* __restrict__ B = z ? B1 : B0;
    float* __restrict__ Cb = C + (long)blockIdx.y * cSplitStride + (long)z * cZStride;

    const int rowBase = blockIdx.x * 128;
    const int kStart = blockIdx.y * kLen;

    const int tr = (tid / 16) * 8;   // micro-tile row within block tile
    const int tc = (tid % 16) * 8;   // micro-tile col

    const float* Ag = A + (long)rowBase * K + kStart;
    const float* Bg = B + (long)kStart * 128;

    float acc[8][8];
#pragma unroll
    for (int i = 0; i < 8; i++)
#pragma unroll
        for (int j = 0; j < 8; j++) acc[i][j] = 0.f;

    float4 aReg[2], bReg[2];

    // prefetch first k-slab into registers
#pragma unroll
    for (int i = 0; i < 2; i++) {
        int li = tid + i * 256;
        int r_ = li >> 2, c4 = li & 3;                        // A: 128 rows x 4 float4
        aReg[i] = *reinterpret_cast<const float4*>(Ag + (long)r_ * K + c4 * 4);
        int kr = li >> 5, b4 = li & 31;                       // B: 16 rows x 32 float4
        bReg[i] = *reinterpret_cast<const float4*>(Bg + (long)kr * 128 + b4 * 4);
    }

    for (int kk = 0; kk < kLen; kk += 16) {
        // registers -> shared
#pragma unroll
        for (int i = 0; i < 2; i++) {
            int li = tid + i * 256;
            int r_ = li >> 2, c4 = (li & 3) * 4;
            As[c4 + 0][r_] = aReg[i].x;
            As[c4 + 1][r_] = aReg[i].y;
            As[c4 + 2][r_] = aReg[i].z;
            As[c4 + 3][r_] = aReg[i].w;
            int kr = li >> 5, b4 = li & 31;
            *reinterpret_cast<float4*>(&Bs[kr][b4 * 4]) = bReg[i];
        }
        __syncthreads();

        // prefetch next slab (overlaps with compute below)
        if (kk + 16 < kLen) {
#pragma unroll
            for (int i = 0; i < 2; i++) {
                int li = tid + i * 256;
                int r_ = li >> 2, c4 = li & 3;
                aReg[i] = *reinterpret_cast<const float4*>(Ag + (long)r_ * K + (kk + 16) + c4 * 4);
                int kr = li >> 5, b4 = li & 31;
                bReg[i] = *reinterpret_cast<const float4*>(Bg + (long)(kk + 16 + kr) * 128 + b4 * 4);
            }
        }

#pragma unroll
        for (int k = 0; k < 16; k++) {
            float a[8], b[8];
            *reinterpret_cast<float4*>(&a[0]) = *reinterpret_cast<const float4*>(&As[k][tr]);
            *reinterpret_cast<float4*>(&a[4]) = *reinterpret_cast<const float4*>(&As[k][tr + 4]);
            *reinterpret_cast<float4*>(&b[0]) = *reinterpret_cast<const float4*>(&Bs[k][tc]);
            *reinterpret_cast<float4*>(&b[4]) = *reinterpret_cast<const float4*>(&Bs[k][tc + 4]);
#pragma unroll
            for (int i = 0; i < 8; i++)
#pragma unroll
                for (int j = 0; j < 8; j++)
                    acc[i][j] = fmaf(a[i], b[j], acc[i][j]);
        }
        __syncthreads();
    }

#pragma unroll
    for (int i = 0; i < 8; i++) {
        float* cr = Cb + (long)(rowBase + tr + i) * 128 + tc;
        *reinterpret_cast<float4*>(cr)     = *reinterpret_cast<float4*>(&acc[i][0]);
        *reinterpret_cast<float4*>(cr + 4) = *reinterpret_cast<float4*>(&acc[i][4]);
    }
}

// ---------------------------------------------------------------------------
// Deterministic split-K reduction: g_partial -> g_umsg, g_imsg
// ---------------------------------------------------------------------------
__global__ void reduce_splits()
{
    int idx = blockIdx.x * blockDim.x + threadIdx.x;
    if (idx >= G_DIM * D_DIM) return;
    const long GD = (long)G_DIM * D_DIM;
    float su = 0.f, si = 0.f;
#pragma unroll
    for (int s = 0; s < SPLITS; s++) {
        su += g_partial[(long)s * GD + idx];
        si += g_partial[(long)(SPLITS + s) * GD + idx];
    }
    g_umsg[idx] = su;
    g_imsg[idx] = si;
}

// ---------------------------------------------------------------------------
// Per-group fusion: class select + concat + [G,384]@W_agg.T + b_agg
// Block = 128 threads (one per output dim d), handles 8 groups to amortize
// W_agg reads (W_agg row d is streamed once per block, reused 8x).
// Notes: argmax(weight,axis=1) over size-1 axis is always 0, so the member
// selection is group_member_embeddings[g,0,:]. Class-1 iff s1 > s0 (argmax
// tie -> 0 preserved).
// ---------------------------------------------------------------------------
__global__ __launch_bounds__(128)
void build_msg(const float* __restrict__ group_emb,
               const float* __restrict__ weight,
               const float* __restrict__ gme,
               const float* __restrict__ W_agg,
               const float* __restrict__ b_agg,
               const float* __restrict__ W_cls,
               const float* __restrict__ b_cls,
               float* __restrict__ msg_out,
               float* __restrict__ pc_out, int write_pc)
{
    __shared__ float xs[8][384];
    const int d = threadIdx.x;
    const int g0 = blockIdx.x * 8;
    const float wc0 = W_cls[0], wc1 = W_cls[1];
    const float bc0 = b_cls[0], bc1 = b_cls[1];

#pragma unroll
    for (int j = 0; j < 8; j++) {
        int g = g0 + j;
        float um  = g_umsg[g * 128 + d];
        float im  = g_imsg[g * 128 + d];
        float ge  = group_emb[g * 128 + d];
        float sel = gme[(long)g * 16 * 128 + d];   // member index 0 always
        float w = weight[g];
        float s0 = w * wc0 + bc0;
        float s1 = w * wc1 + bc1 + BIAS_C;
        int pc = (s1 > s0) ? 1 : 0;
        xs[j][d]       = pc ? sel : um;
        xs[j][128 + d] = im;
        xs[j][256 + d] = im * ge;
        if (d == 0 && write_pc) pc_out[g] = pc ? 1.0f : 0.0f;
    }
    __syncthreads();

    float acc[8];
    float bd = b_agg[d];
#pragma unroll
    for (int j = 0; j < 8; j++) acc[j] = bd;

    const float* wrow = W_agg + (long)d * 384;
    for (int k = 0; k < 384; k += 4) {
        float4 wv = *reinterpret_cast<const float4*>(wrow + k);
#pragma unroll
        for (int j = 0; j < 8; j++) {
            acc[j] = fmaf(xs[j][k],     wv.x, acc[j]);
            acc[j] = fmaf(xs[j][k + 1], wv.y, acc[j]);
            acc[j] = fmaf(xs[j][k + 2], wv.z, acc[j]);
            acc[j] = fmaf(xs[j][k + 3], wv.w, acc[j]);
        }
    }
#pragma unroll
    for (int j = 0; j < 8; j++)
        msg_out[(long)(g0 + j) * 128 + d] = acc[j];
}

// ---------------------------------------------------------------------------
extern "C" void kernel_launch(void* const* d_in, const int* in_sizes, int n_in,
                              void* d_out, int out_size)
{
    const float* user_emb   = (const float*)d_in[0];
    const float* item_emb   = (const float*)d_in[1];
    const float* group_emb  = (const float*)d_in[2];
    const float* user_hg    = (const float*)d_in[3];
    const float* item_hg    = (const float*)d_in[4];
    const float* full_hyper = (const float*)d_in[5];
    const float* weight     = (const float*)d_in[6];
    const float* gme        = (const float*)d_in[7];
    const float* W_agg      = (const float*)d_in[8];
    const float* b_agg      = (const float*)d_in[9];
    const float* W_cls      = (const float*)d_in[10];
    const float* b_cls      = (const float*)d_in[11];
    float* out = (float*)d_out;

    float *partial, *msg_scratch;
    cudaGetSymbolAddress((void**)&partial, g_partial);
    cudaGetSymbolAddress((void**)&msg_scratch, g_msg);

    const long GD = (long)G_DIM * D_DIM;
    const long ND = (long)N_DIM * D_DIM;

    // Output layout assumption: [norm_emb (N*D) | msg (G*D) | predicted (G)]
    // Fall back to scratch for msg if the buffer only holds norm_emb.
    int full_out = (out_size >= (int)(ND + GD + G_DIM));
    float* msg_dst = full_out ? (out + ND) : msg_scratch;
    float* pc_dst  = full_out ? (out + ND + GD) : msg_scratch; // unused if !full_out

    // GEMM 1+2 fused in z: user_msg and item_msg partials (split-K = 16)
    sgemm128<<<dim3(G_DIM / 128, SPLITS, 2), 256>>>(
        user_hg, user_emb, item_hg, item_emb,
        partial, U_DIM, U_DIM / SPLITS, GD, (long)SPLITS * GD);

    reduce_splits<<<(G_DIM * D_DIM) / 256, 256>>>();

    build_msg<<<G_DIM / 8, 128>>>(group_emb, weight, gme, W_agg, b_agg,
                                  W_cls, b_cls, msg_dst, pc_dst, full_out);

    // GEMM 3: norm_emb = full_hyper @ msg (288 tiles, no split-K needed)
    sgemm128<<<dim3(N_DIM / 128, 1, 1), 256>>>(
        full_hyper, msg_dst, full_hyper, msg_dst,
        out, G_DIM, G_DIM, 0, 0);
}

// round 3
// speedup vs baseline: 1.7909x; 1.7909x over previous
#include <cuda_runtime.h>
#include <cuda_fp16.h>
#include <cstdint>

// Problem dimensions (fixed by the dataset)
#define U_DIM 16384
#define G_DIM 4096
#define N_DIM 36864
#define D_DIM 128
#define BIAS_C (-0.73f)
#define SPLITS 4   // split-K for the two G-output GEMMs

// ---------------------------------------------------------------------------
// Scratch (device globals: allocation-free per harness rules)
// ---------------------------------------------------------------------------
__device__ float g_partial[2 * SPLITS * G_DIM * D_DIM];
__device__ float g_umsg[G_DIM * D_DIM];
__device__ float g_imsg[G_DIM * D_DIM];
__device__ float g_msg[G_DIM * D_DIM];
__device__ __half g_bu[(long)U_DIM * D_DIM];   // user_emb fp16 [K,128]
__device__ __half g_bi[(long)U_DIM * D_DIM];   // item_emb fp16 [K,128]
__device__ __half g_bm[(long)G_DIM * D_DIM];   // msg fp16 [K,128]

// ---------------------------------------------------------------------------
// PTX helpers (all compute_103-safe: mma.sync / ldmatrix / cp.async)
// ---------------------------------------------------------------------------
__device__ __forceinline__ uint32_t smem_u32(const void* p) {
    uint32_t a;
    asm("{ .reg .u64 t; cvta.to.shared.u64 t, %1; cvt.u32.u64 %0, t; }" : "=r"(a) : "l"(p));
    return a;
}

#define CP_ASYNC16(dst, src) \
    asm volatile("cp.async.cg.shared.global [%0], [%1], 16;" :: "r"(dst), "l"(src))
#define CP_COMMIT() asm volatile("cp.async.commit_group;" ::: "memory")
#define CP_WAIT0()  asm volatile("cp.async.wait_group 0;" ::: "memory")

#define LDSM_X4(r0, r1, r2, r3, addr) \
    asm volatile("ldmatrix.sync.aligned.m8n8.x4.shared.b16 {%0,%1,%2,%3}, [%4];" \
                 : "=r"(r0), "=r"(r1), "=r"(r2), "=r"(r3) : "r"(addr))
#define LDSM_X4T(r0, r1, r2, r3, addr) \
    asm volatile("ldmatrix.sync.aligned.m8n8.x4.trans.shared.b16 {%0,%1,%2,%3}, [%4];" \
                 : "=r"(r0), "=r"(r1), "=r"(r2), "=r"(r3) : "r"(addr))

#define MMA16816(c, a0, a1, a2, a3, b0, b1) \
    asm volatile("mma.sync.aligned.m16n8k16.row.col.f32.f16.f16.f32 " \
                 "{%0,%1,%2,%3}, {%4,%5,%6,%7}, {%8,%9}, {%0,%1,%2,%3};" \
                 : "+f"((c)[0]), "+f"((c)[1]), "+f"((c)[2]), "+f"((c)[3]) \
                 : "r"(a0), "r"(a1), "r"(a2), "r"(a3), "r"(b0), "r"(b1))

__device__ __forceinline__ uint32_t packh(__half a, __half b) {
    return ((uint32_t)__half_as_ushort(b) << 16) | (uint32_t)__half_as_ushort(a);
}

// ---------------------------------------------------------------------------
// SMEM: double-buffered. Per buffer (48KB): A_hi[128][64]h, A_lo, B[64][128]h.
// XOR swizzle: 16B chunk index c stored at (c ^ (row%8)).
// ---------------------------------------------------------------------------
#define BUF_STRIDE 49152
#define AHI_OFF 0
#define ALO_OFF 16384
#define B_OFF   32768
#define GEMM_SMEM (2 * BUF_STRIDE)

// ---------------------------------------------------------------------------
// C[Mtile=128,128] = A[M,K](fp32, 2-term fp16 split) @ B[K,128](fp16)
// blockIdx: x = M tile, y = K split, z = gemm instance.
// ---------------------------------------------------------------------------
__global__ __launch_bounds__(256)
void gemm_hmma(const float* __restrict__ A0, const __half* __restrict__ B0,
               const float* __restrict__ A1, const __half* __restrict__ B1,
               float* __restrict__ C, int K, int kLen,
               long cSplitStride, long cZStride)
{
    extern __shared__ char smem[];
    const uint32_t sb = smem_u32(smem);
    const int tid = threadIdx.x;
    const int lane = tid & 31, wid = tid >> 5;
    const int wm = wid >> 2, wn = wid & 3;         // 2 x 4 warp grid
    const int z = blockIdx.z;
    const float* __restrict__ A = z ? A1 : A0;
    const __half* __restrict__ B = z ? B1 : B0;
    float* __restrict__ Cb = C + (long)blockIdx.y * cSplitStride + (long)z * cZStride;

    const int rowBase = blockIdx.x * 128;
    const int kStart = blockIdx.y * kLen;
    const int nc = kLen / 64;

    // A prefetch addressing: row = tid/2, 32 cols at (tid&1)*32
    const int ar = tid >> 1;
    const int ach = tid & 1;
    const float* Ap = A + (long)(rowBase + ar) * K + kStart + ach * 32;
    const char* Bg = (const char*)(B + (long)kStart * 128);

    // prologue: cp.async B(0), LDG A(0)
    {
        uint32_t bd = sb + B_OFF;
#pragma unroll
        for (int j = 0; j < 4; j++) {
            int idx = tid * 4 + j;
            int k = idx >> 4, cc = idx & 15;
            uint32_t dst = bd + k * 256 + ((cc ^ (k & 7)) * 16);
            CP_ASYNC16(dst, Bg + k * 256 + cc * 16);
        }
        CP_COMMIT();
    }
    float4 pv[8];
#pragma unroll
    for (int j = 0; j < 8; j++) pv[j] = *reinterpret_cast<const float4*>(Ap + j * 4);

    float acc[4][4][4];
#pragma unroll
    for (int a = 0; a < 4; a++)
#pragma unroll
        for (int b = 0; b < 4; b++)
#pragma unroll
            for (int q = 0; q < 4; q++) acc[a][b][q] = 0.f;

    const uint32_t awbase = (uint32_t)(ar * 128);
    const int r7 = ar & 7;

    for (int c = 0; c < nc; c++) {
        const uint32_t pOff = (uint32_t)(c & 1) * BUF_STRIDE;

        // ---- convert A(c): fp32 regs -> fp16 hi/lo in SMEM (swizzled) ----
#pragma unroll
        for (int j = 0; j < 4; j++) {
            float f0 = pv[2 * j].x, f1 = pv[2 * j].y, f2 = pv[2 * j].z, f3 = pv[2 * j].w;
            float f4 = pv[2 * j + 1].x, f5 = pv[2 * j + 1].y, f6 = pv[2 * j + 1].z, f7 = pv[2 * j + 1].w;
            __half h0 = __float2half_rn(f0), h1 = __float2half_rn(f1);
            __half h2 = __float2half_rn(f2), h3 = __float2half_rn(f3);
            __half h4 = __float2half_rn(f4), h5 = __float2half_rn(f5);
            __half h6 = __float2half_rn(f6), h7 = __float2half_rn(f7);
            uint4 hi, lo;
            hi.x = packh(h0, h1); hi.y = packh(h2, h3);
            hi.z = packh(h4, h5); hi.w = packh(h6, h7);
            lo.x = packh(__float2half_rn(f0 - __half2float(h0)), __float2half_rn(f1 - __half2float(h1)));
            lo.y = packh(__float2half_rn(f2 - __half2float(h2)), __float2half_rn(f3 - __half2float(h3)));
            lo.z = packh(__float2half_rn(f4 - __half2float(h4)), __float2half_rn(f5 - __half2float(h5)));
            lo.w = packh(__float2half_rn(f6 - __half2float(h6)), __float2half_rn(f7 - __half2float(h7)));
            uint32_t chunk = (uint32_t)(((ach * 4 + j) ^ r7) * 16);
            *reinterpret_cast<uint4*>(smem + pOff + AHI_OFF + awbase + chunk) = hi;
            *reinterpret_cast<uint4*>(smem + pOff + ALO_OFF + awbase + chunk) = lo;
        }

        CP_WAIT0();           // B(c) landed (own group); barrier makes all visible
        __syncthreads();

        // ---- issue next-chunk loads (overlap with compute) ----
        if (c + 1 < nc) {
            const float* An = Ap + (c + 1) * 64;
#pragma unroll
            for (int j = 0; j < 8; j++) pv[j] = *reinterpret_cast<const float4*>(An + j * 4);
            uint32_t bd = sb + ((uint32_t)((c + 1) & 1) * BUF_STRIDE) + B_OFF;
            const char* Bn = Bg + (long)(c + 1) * 16384;
#pragma unroll
            for (int j = 0; j < 4; j++) {
                int idx = tid * 4 + j;
                int k = idx >> 4, cc = idx & 15;
                uint32_t dst = bd + k * 256 + ((cc ^ (k & 7)) * 16);
                CP_ASYNC16(dst, Bn + k * 256 + cc * 16);
            }
            CP_COMMIT();
        }

        // ---- compute on buffer p ----
        const uint32_t Ah = sb + pOff + AHI_OFF;
        const uint32_t Al = sb + pOff + ALO_OFF;
        const uint32_t Bs = sb + pOff + B_OFF;
#pragma unroll
        for (int kk = 0; kk < 4; kk++) {
            uint32_t bf[4][2];
#pragma unroll
            for (int h = 0; h < 2; h++) {
                int row = kk * 16 + (lane & 15);
                int nch = (wn * 4 + h * 2 + (lane >> 4)) ^ (row & 7);
                uint32_t r0, r1, r2, r3;
                LDSM_X4T(r0, r1, r2, r3, Bs + row * 256 + nch * 16);
                bf[h * 2][0] = r0; bf[h * 2][1] = r1;
                bf[h * 2 + 1][0] = r2; bf[h * 2 + 1][1] = r3;
            }
#pragma unroll
            for (int im = 0; im < 4; im++) {
                int row = wm * 64 + im * 16 + (lane & 15);
                int kc = (kk * 2 + (lane >> 4)) ^ (row & 7);
                uint32_t a0, a1, a2, a3, l0, l1, l2, l3;
                LDSM_X4(a0, a1, a2, a3, Ah + row * 128 + kc * 16);
                LDSM_X4(l0, l1, l2, l3, Al + row * 128 + kc * 16);
#pragma unroll
                for (int in_ = 0; in_ < 4; in_++) {
                    MMA16816(acc[im][in_], a0, a1, a2, a3, bf[in_][0], bf[in_][1]);
                    MMA16816(acc[im][in_], l0, l1, l2, l3, bf[in_][0], bf[in_][1]);
                }
            }
        }
        __syncthreads();
    }

    // ---- epilogue: write fp32 C ----
#pragma unroll
    for (int im = 0; im < 4; im++) {
#pragma unroll
        for (int in_ = 0; in_ < 4; in_++) {
            long r0w = rowBase + wm * 64 + im * 16 + (lane >> 2);
            int col = wn * 32 + in_ * 8 + (lane & 3) * 2;
            float2 v0 = make_float2(acc[im][in_][0], acc[im][in_][1]);
            float2 v1 = make_float2(acc[im][in_][2], acc[im][in_][3]);
            *reinterpret_cast<float2*>(Cb + r0w * 128 + col) = v0;
            *reinterpret_cast<float2*>(Cb + (r0w + 8) * 128 + col) = v1;
        }
    }
}

// ---------------------------------------------------------------------------
// fp32 -> fp16 elementwise (B operands)
// ---------------------------------------------------------------------------
__global__ void to_half(const float* __restrict__ s, __half* __restrict__ d, int n4)
{
    int i = blockIdx.x * blockDim.x + threadIdx.x;
    if (i < n4) {
        float4 v = reinterpret_cast<const float4*>(s)[i];
        __half2 a = __floats2half2_rn(v.x, v.y);
        __half2 b = __floats2half2_rn(v.z, v.w);
        reinterpret_cast<__half2*>(d)[i * 2] = a;
        reinterpret_cast<__half2*>(d)[i * 2 + 1] = b;
    }
}

// ---------------------------------------------------------------------------
// Deterministic split-K reduction
// ---------------------------------------------------------------------------
__global__ void reduce_splits()
{
    int idx = blockIdx.x * blockDim.x + threadIdx.x;
    if (idx >= G_DIM * D_DIM) return;
    const long GD = (long)G_DIM * D_DIM;
    float su = 0.f, si = 0.f;
#pragma unroll
    for (int s = 0; s < SPLITS; s++) {
        su += g_partial[(long)s * GD + idx];
        si += g_partial[(long)(SPLITS + s) * GD + idx];
    }
    g_umsg[idx] = su;
    g_imsg[idx] = si;
}

// ---------------------------------------------------------------------------
// Per-group fusion (argmax over size-1 axis == 0; class-1 iff s1 > s0)
// ---------------------------------------------------------------------------
__global__ __launch_bounds__(128)
void build_msg(const float* __restrict__ group_emb,
               const float* __restrict__ weight,
               const float* __restrict__ gme,
               const float* __restrict__ W_agg,
               const float* __restrict__ b_agg,
               const float* __restrict__ W_cls,
               const float* __restrict__ b_cls,
               float* __restrict__ msg_out,
               float* __restrict__ pc_out, int write_pc)
{
    __shared__ float xs[8][384];
    const int d = threadIdx.x;
    const int g0 = blockIdx.x * 8;
    const float wc0 = W_cls[0], wc1 = W_cls[1];
    const float bc0 = b_cls[0], bc1 = b_cls[1];

#pragma unroll
    for (int j = 0; j < 8; j++) {
        int g = g0 + j;
        float um  = g_umsg[g * 128 + d];
        float im  = g_imsg[g * 128 + d];
        float ge  = group_emb[g * 128 + d];
        float sel = gme[(long)g * 16 * 128 + d];
        float w = weight[g];
        float s0 = w * wc0 + bc0;
        float s1 = w * wc1 + bc1 + BIAS_C;
        int pc = (s1 > s0) ? 1 : 0;
        xs[j][d]       = pc ? sel : um;
        xs[j][128 + d] = im;
        xs[j][256 + d] = im * ge;
        if (d == 0 && write_pc) pc_out[g] = pc ? 1.0f : 0.0f;
    }
    __syncthreads();

    float acc[8];
    float bd = b_agg[d];
#pragma unroll
    for (int j = 0; j < 8; j++) acc[j] = bd;

    const float* wrow = W_agg + (long)d * 384;
    for (int k = 0; k < 384; k += 4) {
        float4 wv = *reinterpret_cast<const float4*>(wrow + k);
#pragma unroll
        for (int j = 0; j < 8; j++) {
            acc[j] = fmaf(xs[j][k],     wv.x, acc[j]);
            acc[j] = fmaf(xs[j][k + 1], wv.y, acc[j]);
            acc[j] = fmaf(xs[j][k + 2], wv.z, acc[j]);
            acc[j] = fmaf(xs[j][k + 3], wv.w, acc[j]);
        }
    }
#pragma unroll
    for (int j = 0; j < 8; j++)
        msg_out[(long)(g0 + j) * 128 + d] = acc[j];
}

// ---------------------------------------------------------------------------
extern "C" void kernel_launch(void* const* d_in, const int* in_sizes, int n_in,
                              void* d_out, int out_size)
{
    const float* user_emb   = (const float*)d_in[0];
    const float* item_emb   = (const float*)d_in[1];
    const float* group_emb  = (const float*)d_in[2];
    const float* user_hg    = (const float*)d_in[3];
    const float* item_hg    = (const float*)d_in[4];
    const float* full_hyper = (const float*)d_in[5];
    const float* weight     = (const float*)d_in[6];
    const float* gme        = (const float*)d_in[7];
    const float* W_agg      = (const float*)d_in[8];
    const float* b_agg      = (const float*)d_in[9];
    const float* W_cls      = (const float*)d_in[10];
    const float* b_cls      = (const float*)d_in[11];
    float* out = (float*)d_out;

    float *partial, *msg_scratch;
    __half *bu, *bi, *bm;
    cudaGetSymbolAddress((void**)&partial, g_partial);
    cudaGetSymbolAddress((void**)&msg_scratch, g_msg);
    cudaGetSymbolAddress((void**)&bu, g_bu);
    cudaGetSymbolAddress((void**)&bi, g_bi);
    cudaGetSymbolAddress((void**)&bm, g_bm);

    static int smem_set = 0;
    if (!smem_set) {
        cudaFuncSetAttribute(gemm_hmma, cudaFuncAttributeMaxDynamicSharedMemorySize, GEMM_SMEM);
        smem_set = 1;
    }

    const long GD = (long)G_DIM * D_DIM;
    const long ND = (long)N_DIM * D_DIM;

    int full_out = (out_size >= (int)(ND + GD + G_DIM));
    float* msg_dst = full_out ? (out + ND) : msg_scratch;
    float* pc_dst  = full_out ? (out + ND + GD) : msg_scratch;

    // B operands -> fp16
    to_half<<<(U_DIM * D_DIM / 4 + 255) / 256, 256>>>(user_emb, bu, U_DIM * D_DIM / 4);
    to_half<<<(U_DIM * D_DIM / 4 + 255) / 256, 256>>>(item_emb, bi, U_DIM * D_DIM / 4);

    // GEMM 1+2 (user_msg, item_msg): split-K partials
    gemm_hmma<<<dim3(G_DIM / 128, SPLITS, 2), 256, GEMM_SMEM>>>(
        user_hg, bu, item_hg, bi,
        partial, U_DIM, U_DIM / SPLITS, GD, (long)SPLITS * GD);

    reduce_splits<<<(G_DIM * D_DIM) / 256, 256>>>();

    build_msg<<<G_DIM / 8, 128>>>(group_emb, weight, gme, W_agg, b_agg,
                                  W_cls, b_cls, msg_dst, pc_dst, full_out);

    to_half<<<(G_DIM * D_DIM / 4 + 255) / 256, 256>>>(msg_dst, bm, G_DIM * D_DIM / 4);

    // GEMM 3: norm_emb = full_hyper @ msg
    gemm_hmma<<<dim3(N_DIM / 128, 1, 1), 256, GEMM_SMEM>>>(
        full_hyper, bm, full_hyper, bm,
        out, G_DIM, G_DIM, 0, 0);
}